// round 10
// baseline (speedup 1.0000x reference)
#include <cuda_runtime.h>
#include <cuda_fp16.h>
#include <cstdint>

// Causal attention B=2,H=16,S=2048,D=64 fp32. fp16 mma.sync m16n8k16.
// R10: identical math/sync to R9, but 3 CTAs/SM (launch_bounds(128,3)) to
// get 3 warps/SMSP: covers the softmax bubble that idles the tensor pipe.

#define S_LEN 2048
#define DH    64
#define BR    128
#define BC    64
#define NT    128
#define NQT   (S_LEN/BR)                 // 16
#define BH_N  32
#define NJOBS (NQT*BH_N)                 // 512
#define NCTA  444                        // 3 per SM
#define KPAD  72
#define ROWB  (KPAD*2)                   // 144 bytes per smem row
#define SC_LOG2E 0.1803368801111204f     // (1/8)*log2(e)
#define NEGINF __int_as_float(0xff800000)

#define KV_ELEMS ((size_t)BH_N * S_LEN * DH)
__device__ __align__(16) __half g_Kh[KV_ELEMS];
__device__ __align__(16) __half g_Vh[KV_ELEMS];
__device__ int g_job;

__device__ __forceinline__ uint32_t smem_u32(const void* p){
    uint32_t a;
    asm("{ .reg .u64 t; cvta.to.shared.u64 t, %1; cvt.u32.u64 %0, t; }" : "=r"(a) : "l"(p));
    return a;
}
__device__ __forceinline__ uint32_t h2(float a, float b){
    __half2 v = __floats2half2_rn(a, b);
    return *reinterpret_cast<uint32_t*>(&v);
}
__device__ __forceinline__ uint32_t ex2h2(uint32_t x){
    uint32_t y; asm("ex2.approx.f16x2 %0, %1;" : "=r"(y) : "r"(x)); return y;
}
__device__ __forceinline__ void ldm_x4(uint32_t r[4], uint32_t addr){
    asm volatile("ldmatrix.sync.aligned.m8n8.x4.shared.b16 {%0,%1,%2,%3}, [%4];"
                 : "=r"(r[0]), "=r"(r[1]), "=r"(r[2]), "=r"(r[3]) : "r"(addr));
}
__device__ __forceinline__ void ldm_x4_t(uint32_t r[4], uint32_t addr){
    asm volatile("ldmatrix.sync.aligned.m8n8.x4.trans.shared.b16 {%0,%1,%2,%3}, [%4];"
                 : "=r"(r[0]), "=r"(r[1]), "=r"(r[2]), "=r"(r[3]) : "r"(addr));
}
__device__ __forceinline__ void mma_f16(float d[4], const uint32_t a[4],
                                        const uint32_t b[2]){
    asm volatile(
        "mma.sync.aligned.m16n8k16.row.col.f32.f16.f16.f32 "
        "{%0,%1,%2,%3}, {%4,%5,%6,%7}, {%8,%9}, {%0,%1,%2,%3};"
        : "+f"(d[0]), "+f"(d[1]), "+f"(d[2]), "+f"(d[3])
        : "r"(a[0]), "r"(a[1]), "r"(a[2]), "r"(a[3]),
          "r"(b[0]), "r"(b[1]));
}
__device__ __forceinline__ void cp16(uint32_t dst, const void* src){
    asm volatile("cp.async.cg.shared.global [%0], [%1], 16;" :: "r"(dst), "l"(src));
}
#define CP_COMMIT() asm volatile("cp.async.commit_group;")
#define CP_WAIT0()  asm volatile("cp.async.wait_group 0;")

// ---- pre-pass: fp32 -> fp16 K,V ; reset job counter ----
__global__ void __launch_bounds__(256) convKV(const float* __restrict__ K,
                                              const float* __restrict__ V){
    if (blockIdx.x == 0 && threadIdx.x == 0) g_job = 0;
    size_t i = ((size_t)blockIdx.x * 256 + threadIdx.x) * 4;
    float4 k = *reinterpret_cast<const float4*>(K + i);
    float4 v = *reinterpret_cast<const float4*>(V + i);
    uint2 ku; ku.x = h2(k.x, k.y); ku.y = h2(k.z, k.w);
    uint2 vu; vu.x = h2(v.x, v.y); vu.y = h2(v.z, v.w);
    *reinterpret_cast<uint2*>(&g_Kh[i]) = ku;
    *reinterpret_cast<uint2*>(&g_Vh[i]) = vu;
}

__global__ void __launch_bounds__(NT, 3) attn_f16(
    const float* __restrict__ Q, float* __restrict__ O)
{
    __shared__ __align__(16) __half Ksm[2][BC][KPAD];
    __shared__ __align__(16) __half Vsm[2][BC][KPAD];
    __shared__ int sjob;

    const int t = threadIdx.x, lane = t & 31, w = t >> 5;   // w in 0..3
    const int g = lane >> 2, j = lane & 3;

    const uint32_t ks0 = smem_u32(&Ksm[0][0][0]);
    const uint32_t vs0 = smem_u32(&Vsm[0][0][0]);
    const uint32_t kmoff = (uint32_t)((lane & 7) * ROWB + (lane >> 3) * 16);
    const uint32_t vmoff = (uint32_t)(lane * ROWB);

    // cp.async map: 4 chunks per matrix per thread (64 rows x 8 chunks = 512)
    uint32_t kds[4], vds[4];
    int ld_e[4];
    #pragma unroll
    for (int i = 0; i < 4; i++) {
        int idx = t + i * NT;
        int row = idx >> 3, chb = (idx & 7) * 16;
        kds[i] = ks0 + (uint32_t)(row * ROWB + chb);
        vds[i] = vs0 + (uint32_t)(row * ROWB + chb);
        ld_e[i] = row * DH + (chb >> 1);
    }

    // constant ones-column B fragment (col n=0 lives in lanes 0..3)
    const uint32_t bones = (lane < 4) ? 0x3C003C00u : 0u;
    const uint32_t bsum[2] = {bones, bones};

    while (true) {
        if (t == 0) sjob = atomicAdd(&g_job, 1);
        __syncthreads();
        const int job = sjob;
        if (job >= NJOBS) break;
        const int q  = (NQT - 1) - (job >> 5);
        const int bh = job & 31;
        const int nkt = 2 * (q + 1);
        const size_t base = (size_t)bh * S_LEN * DH;
        const __half* Kh = g_Kh + base;
        const __half* Vh = g_Vh + base;
        const int rbase = q * BR + w * 32;          // warp's first q row
        const int wrow_max = rbase + 31;

        // tile 0 loads (buffer 0)
        #pragma unroll
        for (int i = 0; i < 4; i++) {
            cp16(kds[i], Kh + ld_e[i]);
            cp16(vds[i], Vh + ld_e[i]);
        }
        CP_COMMIT();

        // Q -> fp16 A-fragments, two row blocks, pre-scaled by (1/8)*log2(e)
        uint32_t aq[2][4][4];
        #pragma unroll
        for (int rb = 0; rb < 2; rb++) {
            const float* q0 = Q + base + (size_t)(rbase + rb * 16 + g) * DH;
            const float* q1 = q0 + 8 * DH;
            #pragma unroll
            for (int kb = 0; kb < 4; kb++) {
                float2 x0 = *(const float2*)(q0 + kb * 16 + 2 * j);
                float2 x1 = *(const float2*)(q1 + kb * 16 + 2 * j);
                float2 x2 = *(const float2*)(q0 + kb * 16 + 2 * j + 8);
                float2 x3 = *(const float2*)(q1 + kb * 16 + 2 * j + 8);
                aq[rb][kb][0] = h2(x0.x * SC_LOG2E, x0.y * SC_LOG2E);
                aq[rb][kb][1] = h2(x1.x * SC_LOG2E, x1.y * SC_LOG2E);
                aq[rb][kb][2] = h2(x2.x * SC_LOG2E, x2.y * SC_LOG2E);
                aq[rb][kb][3] = h2(x3.x * SC_LOG2E, x3.y * SC_LOG2E);
            }
        }

        float o0[9][4], o1[9][4];
        #pragma unroll
        for (int n = 0; n < 9; n++)
            #pragma unroll
            for (int x = 0; x < 4; x++) { o0[n][x] = 0.f; o1[n][x] = 0.f; }

        for (int kt = 0; kt < nkt; kt++) {
            const uint32_t bufo = (uint32_t)((kt & 1) ? BC * ROWB : 0);

            CP_WAIT0();                  // my tile-kt chunks complete
            __syncthreads();             // publish all; WAR-safe other buffer

            if (kt + 1 < nkt) {          // prefetch kt+1 (overlaps compute)
                const uint32_t nb = (uint32_t)(((kt + 1) & 1) ? BC * ROWB : 0);
                const __half* Kp = Kh + (size_t)(kt + 1) * BC * DH;
                const __half* Vp = Vh + (size_t)(kt + 1) * BC * DH;
                #pragma unroll
                for (int i = 0; i < 4; i++) {
                    cp16(kds[i] + nb, Kp + ld_e[i]);
                    cp16(vds[i] + nb, Vp + ld_e[i]);
                }
                CP_COMMIT();
            }

            if (kt * 64 > wrow_max) continue;    // fully masked for this warp

            // ---- MMA1 (both row blocks share K fragments) + fused softmax ----
            const uint32_t ksb = ks0 + bufo;
            const bool hasmask = (kt >= 2 * q);
            uint32_t apA0[8], apA1[8], apB0[8], apB1[8];
            #pragma unroll
            for (int nt = 0; nt < 8; nt++) {
                uint32_t b[8];
                uint32_t a0 = ksb + (uint32_t)(nt * 8 * ROWB) + kmoff;
                ldm_x4(b,     a0);
                ldm_x4(b + 4, a0 + 64);
                float sA[4] = {0.f, 0.f, 0.f, 0.f};
                float sB[4] = {0.f, 0.f, 0.f, 0.f};
                #pragma unroll
                for (int kb = 0; kb < 4; kb++) {
                    mma_f16(sA, aq[0][kb], b + 2 * kb);
                    mma_f16(sB, aq[1][kb], b + 2 * kb);
                }
                if (hasmask) {
                    int c0 = kt * 64 + nt * 8 + 2 * j;
                    int rA = rbase + g, rB = rA + 16;
                    if (c0     > rA)      sA[0] = NEGINF;
                    if (c0 + 1 > rA)      sA[1] = NEGINF;
                    if (c0     > rA + 8)  sA[2] = NEGINF;
                    if (c0 + 1 > rA + 8)  sA[3] = NEGINF;
                    if (c0     > rB)      sB[0] = NEGINF;
                    if (c0 + 1 > rB)      sB[1] = NEGINF;
                    if (c0     > rB + 8)  sB[2] = NEGINF;
                    if (c0 + 1 > rB + 8)  sB[3] = NEGINF;
                }
                apA0[nt] = ex2h2(h2(sA[0], sA[1]));
                apA1[nt] = ex2h2(h2(sA[2], sA[3]));
                apB0[nt] = ex2h2(h2(sB[0], sB[1]));
                apB1[nt] = ex2h2(h2(sB[2], sB[3]));
            }

            // ---- MMA2 (both row blocks share V fragments) ----
            const uint32_t vsb = vs0 + bufo;
            #pragma unroll
            for (int nb2 = 0; nb2 < 8; nb2++) {
                uint32_t b[8];
                uint32_t a0 = vsb + vmoff + (uint32_t)(nb2 * 16);
                ldm_x4_t(b,     a0);
                ldm_x4_t(b + 4, a0 + 32 * ROWB);
                #pragma unroll
                for (int kb = 0; kb < 4; kb++) {
                    uint32_t A0[4] = {apA0[2 * kb], apA1[2 * kb],
                                      apA0[2 * kb + 1], apA1[2 * kb + 1]};
                    uint32_t A1[4] = {apB0[2 * kb], apB1[2 * kb],
                                      apB0[2 * kb + 1], apB1[2 * kb + 1]};
                    mma_f16(o0[nb2], A0, b + 2 * kb);
                    mma_f16(o1[nb2], A1, b + 2 * kb);
                }
            }
            #pragma unroll
            for (int kb = 0; kb < 4; kb++) {     // row sums, no LDSM
                uint32_t A0[4] = {apA0[2 * kb], apA1[2 * kb],
                                  apA0[2 * kb + 1], apA1[2 * kb + 1]};
                uint32_t A1[4] = {apB0[2 * kb], apB1[2 * kb],
                                  apB0[2 * kb + 1], apB1[2 * kb + 1]};
                mma_f16(o0[8], A0, bsum);
                mma_f16(o1[8], A1, bsum);
            }
        }

        // ---- epilogue ----
        const float sA0 = __shfl_sync(0xffffffffu, o0[8][0], lane & 28);
        const float sA1 = __shfl_sync(0xffffffffu, o0[8][2], lane & 28);
        const float sB0 = __shfl_sync(0xffffffffu, o1[8][0], lane & 28);
        const float sB1 = __shfl_sync(0xffffffffu, o1[8][2], lane & 28);
        const float iA0 = 1.0f / sA0, iA1 = 1.0f / sA1;
        const float iB0 = 1.0f / sB0, iB1 = 1.0f / sB1;

        float* oA = O + base + (size_t)(rbase + g) * DH;
        float* oB = oA + 16 * DH;
        #pragma unroll
        for (int nb2 = 0; nb2 < 8; nb2++) {
            int c = nb2 * 8 + 2 * j;
            *(float2*)(oA + c)          = make_float2(o0[nb2][0] * iA0, o0[nb2][1] * iA0);
            *(float2*)(oA + 8 * DH + c) = make_float2(o0[nb2][2] * iA1, o0[nb2][3] * iA1);
            *(float2*)(oB + c)          = make_float2(o1[nb2][0] * iB0, o1[nb2][1] * iB0);
            *(float2*)(oB + 8 * DH + c) = make_float2(o1[nb2][2] * iB1, o1[nb2][3] * iB1);
        }
    }
}

extern "C" void kernel_launch(void* const* d_in, const int* in_sizes, int n_in,
                              void* d_out, int out_size)
{
    const float* Q = (const float*)d_in[0];
    const float* K = (const float*)d_in[1];
    const float* V = (const float*)d_in[2];
    float* O = (float*)d_out;

    convKV<<<(int)(KV_ELEMS / 4 / 256), 256>>>(K, V);
    attn_f16<<<NCTA, NT>>>(Q, O);
}

// round 11
// speedup vs baseline: 1.4866x; 1.4866x over previous
#include <cuda_runtime.h>
#include <cuda_fp16.h>
#include <cstdint>

// Causal attention B=2,H=16,S=2048,D=64 fp32. fp16 mma.sync m16n8k16.
// R11: R9 math/sync, restructured for >=4 independent HMMA chains
// (MMA1 nt-pairs, MMA2 kb-outer/nb-groups, k-half split). 2 CTAs/SM.

#define S_LEN 2048
#define DH    64
#define BR    128
#define BC    64
#define NT    128
#define NQT   (S_LEN/BR)                 // 16
#define BH_N  32
#define NJOBS (NQT*BH_N)                 // 512
#define NCTA  296                        // 2 per SM
#define KPAD  72
#define ROWB  (KPAD*2)                   // 144 bytes per smem row
#define SC_LOG2E 0.1803368801111204f     // (1/8)*log2(e)
#define NEGINF __int_as_float(0xff800000)

#define KV_ELEMS ((size_t)BH_N * S_LEN * DH)
__device__ __align__(16) __half g_Kh[KV_ELEMS];
__device__ __align__(16) __half g_Vh[KV_ELEMS];
__device__ int g_job;

__device__ __forceinline__ uint32_t smem_u32(const void* p){
    uint32_t a;
    asm("{ .reg .u64 t; cvta.to.shared.u64 t, %1; cvt.u32.u64 %0, t; }" : "=r"(a) : "l"(p));
    return a;
}
__device__ __forceinline__ uint32_t h2(float a, float b){
    __half2 v = __floats2half2_rn(a, b);
    return *reinterpret_cast<uint32_t*>(&v);
}
__device__ __forceinline__ uint32_t ex2h2(uint32_t x){
    uint32_t y; asm("ex2.approx.f16x2 %0, %1;" : "=r"(y) : "r"(x)); return y;
}
__device__ __forceinline__ void ldm_x4(uint32_t r[4], uint32_t addr){
    asm volatile("ldmatrix.sync.aligned.m8n8.x4.shared.b16 {%0,%1,%2,%3}, [%4];"
                 : "=r"(r[0]), "=r"(r[1]), "=r"(r[2]), "=r"(r[3]) : "r"(addr));
}
__device__ __forceinline__ void ldm_x4_t(uint32_t r[4], uint32_t addr){
    asm volatile("ldmatrix.sync.aligned.m8n8.x4.trans.shared.b16 {%0,%1,%2,%3}, [%4];"
                 : "=r"(r[0]), "=r"(r[1]), "=r"(r[2]), "=r"(r[3]) : "r"(addr));
}
__device__ __forceinline__ void mma_f16(float d[4], const uint32_t a[4],
                                        const uint32_t b[2]){
    asm volatile(
        "mma.sync.aligned.m16n8k16.row.col.f32.f16.f16.f32 "
        "{%0,%1,%2,%3}, {%4,%5,%6,%7}, {%8,%9}, {%0,%1,%2,%3};"
        : "+f"(d[0]), "+f"(d[1]), "+f"(d[2]), "+f"(d[3])
        : "r"(a[0]), "r"(a[1]), "r"(a[2]), "r"(a[3]),
          "r"(b[0]), "r"(b[1]));
}
__device__ __forceinline__ void cp16(uint32_t dst, const void* src){
    asm volatile("cp.async.cg.shared.global [%0], [%1], 16;" :: "r"(dst), "l"(src));
}
#define CP_COMMIT() asm volatile("cp.async.commit_group;")
#define CP_WAIT0()  asm volatile("cp.async.wait_group 0;")

// ---- pre-pass: fp32 -> fp16 K,V ; reset job counter ----
__global__ void __launch_bounds__(256) convKV(const float* __restrict__ K,
                                              const float* __restrict__ V){
    if (blockIdx.x == 0 && threadIdx.x == 0) g_job = 0;
    size_t i = ((size_t)blockIdx.x * 256 + threadIdx.x) * 4;
    float4 k = *reinterpret_cast<const float4*>(K + i);
    float4 v = *reinterpret_cast<const float4*>(V + i);
    uint2 ku; ku.x = h2(k.x, k.y); ku.y = h2(k.z, k.w);
    uint2 vu; vu.x = h2(v.x, v.y); vu.y = h2(v.z, v.w);
    *reinterpret_cast<uint2*>(&g_Kh[i]) = ku;
    *reinterpret_cast<uint2*>(&g_Vh[i]) = vu;
}

__global__ void __launch_bounds__(NT, 2) attn_f16(
    const float* __restrict__ Q, float* __restrict__ O)
{
    __shared__ __align__(16) __half Ksm[2][BC][KPAD];
    __shared__ __align__(16) __half Vsm[2][BC][KPAD];
    __shared__ int sjob;

    const int t = threadIdx.x, lane = t & 31, w = t >> 5;   // w in 0..3
    const int g = lane >> 2, j = lane & 3;

    const uint32_t ks0 = smem_u32(&Ksm[0][0][0]);
    const uint32_t vs0 = smem_u32(&Vsm[0][0][0]);
    const uint32_t kmoff = (uint32_t)((lane & 7) * ROWB + (lane >> 3) * 16);
    const uint32_t vmoff = (uint32_t)(lane * ROWB);

    // cp.async map: 4 chunks per matrix per thread
    uint32_t kds[4], vds[4];
    int ld_e[4];
    #pragma unroll
    for (int i = 0; i < 4; i++) {
        int idx = t + i * NT;
        int row = idx >> 3, chb = (idx & 7) * 16;
        kds[i] = ks0 + (uint32_t)(row * ROWB + chb);
        vds[i] = vs0 + (uint32_t)(row * ROWB + chb);
        ld_e[i] = row * DH + (chb >> 1);
    }

    const uint32_t bones = (lane < 4) ? 0x3C003C00u : 0u;   // ones col, lanes 0..3
    const uint32_t bsum[2] = {bones, bones};

    while (true) {
        if (t == 0) sjob = atomicAdd(&g_job, 1);
        __syncthreads();
        const int job = sjob;
        if (job >= NJOBS) break;
        const int q  = (NQT - 1) - (job >> 5);
        const int bh = job & 31;
        const int nkt = 2 * (q + 1);
        const size_t base = (size_t)bh * S_LEN * DH;
        const __half* Kh = g_Kh + base;
        const __half* Vh = g_Vh + base;
        const int rbase = q * BR + w * 32;
        const int wrow_max = rbase + 31;

        #pragma unroll
        for (int i = 0; i < 4; i++) {
            cp16(kds[i], Kh + ld_e[i]);
            cp16(vds[i], Vh + ld_e[i]);
        }
        CP_COMMIT();

        // Q -> fp16 A-fragments, pre-scaled by (1/8)*log2(e)
        uint32_t aq[2][4][4];
        #pragma unroll
        for (int rb = 0; rb < 2; rb++) {
            const float* q0 = Q + base + (size_t)(rbase + rb * 16 + g) * DH;
            const float* q1 = q0 + 8 * DH;
            #pragma unroll
            for (int kb = 0; kb < 4; kb++) {
                float2 x0 = *(const float2*)(q0 + kb * 16 + 2 * j);
                float2 x1 = *(const float2*)(q1 + kb * 16 + 2 * j);
                float2 x2 = *(const float2*)(q0 + kb * 16 + 2 * j + 8);
                float2 x3 = *(const float2*)(q1 + kb * 16 + 2 * j + 8);
                aq[rb][kb][0] = h2(x0.x * SC_LOG2E, x0.y * SC_LOG2E);
                aq[rb][kb][1] = h2(x1.x * SC_LOG2E, x1.y * SC_LOG2E);
                aq[rb][kb][2] = h2(x2.x * SC_LOG2E, x2.y * SC_LOG2E);
                aq[rb][kb][3] = h2(x3.x * SC_LOG2E, x3.y * SC_LOG2E);
            }
        }

        float o0[9][4], o1[9][4];
        #pragma unroll
        for (int n = 0; n < 9; n++)
            #pragma unroll
            for (int x = 0; x < 4; x++) { o0[n][x] = 0.f; o1[n][x] = 0.f; }

        for (int kt = 0; kt < nkt; kt++) {
            const uint32_t bufo = (uint32_t)((kt & 1) ? BC * ROWB : 0);

            CP_WAIT0();
            __syncthreads();

            if (kt + 1 < nkt) {
                const uint32_t nb = (uint32_t)(((kt + 1) & 1) ? BC * ROWB : 0);
                const __half* Kp = Kh + (size_t)(kt + 1) * BC * DH;
                const __half* Vp = Vh + (size_t)(kt + 1) * BC * DH;
                #pragma unroll
                for (int i = 0; i < 4; i++) {
                    cp16(kds[i] + nb, Kp + ld_e[i]);
                    cp16(vds[i] + nb, Vp + ld_e[i]);
                }
                CP_COMMIT();
            }

            if (kt * 64 > wrow_max) continue;

            const uint32_t ksb = ks0 + bufo;
            const uint32_t vsb = vs0 + bufo;
            const bool hasmask = (kt >= 2 * q);

            // ---- two k-halves of 32 cols each ----
            #pragma unroll
            for (int h = 0; h < 2; h++) {
                // MMA1: nt = 4h..4h+3, processed as 2 pairs -> 4 live chains
                uint32_t apA0[4], apA1[4], apB0[4], apB1[4];
                #pragma unroll
                for (int ntp = 0; ntp < 2; ntp++) {
                    const int nt0 = 4 * h + 2 * ntp;
                    uint32_t b0[8], b1[8];
                    uint32_t a0 = ksb + (uint32_t)(nt0 * 8 * ROWB) + kmoff;
                    uint32_t a1 = a0 + 8 * ROWB;
                    ldm_x4(b0,     a0);
                    ldm_x4(b0 + 4, a0 + 64);
                    ldm_x4(b1,     a1);
                    ldm_x4(b1 + 4, a1 + 64);

                    float sA0[4] = {0,0,0,0}, sB0[4] = {0,0,0,0};
                    float sA1[4] = {0,0,0,0}, sB1[4] = {0,0,0,0};
                    #pragma unroll
                    for (int kb = 0; kb < 4; kb++) {       // 4 chains round-robin
                        mma_f16(sA0, aq[0][kb], b0 + 2 * kb);
                        mma_f16(sB0, aq[1][kb], b0 + 2 * kb);
                        mma_f16(sA1, aq[0][kb], b1 + 2 * kb);
                        mma_f16(sB1, aq[1][kb], b1 + 2 * kb);
                    }

                    #pragma unroll
                    for (int u = 0; u < 2; u++) {          // u=0 -> nt0, u=1 -> nt0+1
                        float* sA = u ? sA1 : sA0;
                        float* sB = u ? sB1 : sB0;
                        if (hasmask) {
                            int c0 = kt * 64 + (nt0 + u) * 8 + 2 * j;
                            int rA = rbase + g, rB = rA + 16;
                            if (c0     > rA)      sA[0] = NEGINF;
                            if (c0 + 1 > rA)      sA[1] = NEGINF;
                            if (c0     > rA + 8)  sA[2] = NEGINF;
                            if (c0 + 1 > rA + 8)  sA[3] = NEGINF;
                            if (c0     > rB)      sB[0] = NEGINF;
                            if (c0 + 1 > rB)      sB[1] = NEGINF;
                            if (c0     > rB + 8)  sB[2] = NEGINF;
                            if (c0 + 1 > rB + 8)  sB[3] = NEGINF;
                        }
                        apA0[2 * ntp + u] = ex2h2(h2(sA[0], sA[1]));
                        apA1[2 * ntp + u] = ex2h2(h2(sA[2], sA[3]));
                        apB0[2 * ntp + u] = ex2h2(h2(sB[0], sB[1]));
                        apB1[2 * ntp + u] = ex2h2(h2(sB[2], sB[3]));
                    }
                }

                // A-fragments for the 2 local kb steps of this half
                uint32_t A0[2][4], A1[2][4];
                #pragma unroll
                for (int kb = 0; kb < 2; kb++) {
                    A0[kb][0] = apA0[2 * kb];     A0[kb][1] = apA1[2 * kb];
                    A0[kb][2] = apA0[2 * kb + 1]; A0[kb][3] = apA1[2 * kb + 1];
                    A1[kb][0] = apB0[2 * kb];     A1[kb][1] = apB1[2 * kb];
                    A1[kb][2] = apB0[2 * kb + 1]; A1[kb][3] = apB1[2 * kb + 1];
                }

                // MMA2 half: nb groups of 3, kb-outer/nb-inner -> 6 chains
                const uint32_t vh = vsb + vmoff + (uint32_t)(h * 32 * ROWB);
                #pragma unroll
                for (int nbg = 0; nbg < 3; nbg++) {
                    uint32_t bv[3][4];
                    #pragma unroll
                    for (int e = 0; e < 3; e++)
                        ldm_x4_t(bv[e], vh + (uint32_t)((nbg * 3 + e) * 16));
                    #pragma unroll
                    for (int kb = 0; kb < 2; kb++) {
                        #pragma unroll
                        for (int e = 0; e < 3; e++) {
                            const int nb2 = nbg * 3 + e;
                            if (nb2 < 8) {
                                mma_f16(o0[nb2], A0[kb], bv[e] + 2 * kb);
                                mma_f16(o1[nb2], A1[kb], bv[e] + 2 * kb);
                            }
                        }
                    }
                }
                // row sums (constant ones fragment), 2 chains depth 2
                #pragma unroll
                for (int kb = 0; kb < 2; kb++) {
                    mma_f16(o0[8], A0[kb], bsum);
                    mma_f16(o1[8], A1[kb], bsum);
                }
            }
        }

        // ---- epilogue ----
        const float sA0 = __shfl_sync(0xffffffffu, o0[8][0], lane & 28);
        const float sA1 = __shfl_sync(0xffffffffu, o0[8][2], lane & 28);
        const float sB0 = __shfl_sync(0xffffffffu, o1[8][0], lane & 28);
        const float sB1 = __shfl_sync(0xffffffffu, o1[8][2], lane & 28);
        const float iA0 = 1.0f / sA0, iA1 = 1.0f / sA1;
        const float iB0 = 1.0f / sB0, iB1 = 1.0f / sB1;

        float* oA = O + base + (size_t)(rbase + g) * DH;
        float* oB = oA + 16 * DH;
        #pragma unroll
        for (int nb2 = 0; nb2 < 8; nb2++) {
            int c = nb2 * 8 + 2 * j;
            *(float2*)(oA + c)          = make_float2(o0[nb2][0] * iA0, o0[nb2][1] * iA0);
            *(float2*)(oA + 8 * DH + c) = make_float2(o0[nb2][2] * iA1, o0[nb2][3] * iA1);
            *(float2*)(oB + c)          = make_float2(o1[nb2][0] * iB0, o1[nb2][1] * iB0);
            *(float2*)(oB + 8 * DH + c) = make_float2(o1[nb2][2] * iB1, o1[nb2][3] * iB1);
        }
    }
}

extern "C" void kernel_launch(void* const* d_in, const int* in_sizes, int n_in,
                              void* d_out, int out_size)
{
    const float* Q = (const float*)d_in[0];
    const float* K = (const float*)d_in[1];
    const float* V = (const float*)d_in[2];
    float* O = (float*)d_out;

    convKV<<<(int)(KV_ELEMS / 4 / 256), 256>>>(K, V);
    attn_f16<<<NCTA, NT>>>(Q, O);
}